// round 13
// baseline (speedup 1.0000x reference)
#include <cuda_runtime.h>
#include <cuda_bf16.h>
#include <math.h>
#include <stdint.h>

#define B_  1024
#define L_  50
#define D_  4
#define H_  512
#define T_  30
#define N4H 2048
#define CW  516

typedef __nv_bfloat16 bf16;

// ===================== base-ISA PTX helpers (sm_80+ features only) =====================
__device__ __forceinline__ uint32_t smem_u32(const void* p) {
    uint32_t a;
    asm("{ .reg .u64 t; cvta.to.shared.u64 t, %1; cvt.u32.u64 %0, t; }" : "=r"(a) : "l"(p));
    return a;
}
__device__ __forceinline__ void mma16816(float* d, const uint32_t* a, const uint32_t* b) {
    asm volatile(
        "mma.sync.aligned.m16n8k16.row.col.f32.bf16.bf16.f32 "
        "{%0,%1,%2,%3}, {%4,%5,%6,%7}, {%8,%9}, {%0,%1,%2,%3};"
        : "+f"(d[0]), "+f"(d[1]), "+f"(d[2]), "+f"(d[3])
        : "r"(a[0]), "r"(a[1]), "r"(a[2]), "r"(a[3]), "r"(b[0]), "r"(b[1]));
}
__device__ __forceinline__ void ldsm4(uint32_t* r, uint32_t addr) {
    asm volatile("ldmatrix.sync.aligned.m8n8.x4.shared.b16 {%0,%1,%2,%3}, [%4];"
        : "=r"(r[0]), "=r"(r[1]), "=r"(r[2]), "=r"(r[3]) : "r"(addr));
}
// .cg = bypass L1 (dynamic operands), .ca = cache in L1 (static weights)
#define CP_ASYNC_CG16(sa, gp) \
    asm volatile("cp.async.cg.shared.global [%0], [%1], 16;" :: "r"(sa), "l"(gp) : "memory")
#define CP_ASYNC_CA16(sa, gp) \
    asm volatile("cp.async.ca.shared.global [%0], [%1], 16;" :: "r"(sa), "l"(gp) : "memory")
#define CP_COMMIT() asm volatile("cp.async.commit_group;" ::: "memory")

__device__ __forceinline__ float sigf(float x) { return 1.f / (1.f + __expf(-x)); }
__device__ __forceinline__ void bsplit(float v, bf16& hi, bf16& lo) {
    hi = __float2bfloat16(v);
    lo = __float2bfloat16(v - __bfloat162float(hi));
}

// ============================ persistent device state ============================
__device__ __align__(16) float g_hA[B_ * H_];
__device__ __align__(16) float g_hB[B_ * H_];
__device__ __align__(16) bf16  g_hAh[B_ * H_];
__device__ __align__(16) bf16  g_hAl[B_ * H_];
__device__ __align__(16) bf16  g_hBh[B_ * H_];
__device__ __align__(16) bf16  g_hBl[B_ * H_];
__device__ __align__(16) float g_c[B_ * H_];
__device__ __align__(16) float g_enc[B_ * L_ * H_];
__device__ __align__(16) bf16  g_attnH[B_ * H_];
__device__ __align__(16) bf16  g_attnL[B_ * H_];
__device__ __align__(16) bf16  g_combH[B_ * H_];
__device__ __align__(16) bf16  g_combL[B_ * H_];
__device__ __align__(16) float g_xA[B_ * D_];
__device__ __align__(16) float g_xB[B_ * D_];
// gate-permuted weights for fused LSTM epilogue:
// new col n: chunk=n>>4, w=n&15, gate=((w>>3)<<1)|(w&1), unit=chunk*4+((w>>1)&3)
__device__ __align__(16) bf16  g_WencHHh[N4H * H_];
__device__ __align__(16) bf16  g_WencHHl[N4H * H_];
__device__ __align__(16) bf16  g_WdecIHh[N4H * H_];
__device__ __align__(16) bf16  g_WdecIHl[N4H * H_];
__device__ __align__(16) bf16  g_WdecHHh[N4H * H_];
__device__ __align__(16) bf16  g_WdecHHl[N4H * H_];
__device__ __align__(16) float g_WencIH[N4H * D_];
__device__ __align__(16) bf16  g_combWh[H_ * H_];
__device__ __align__(16) bf16  g_combWl[H_ * H_];
__device__ __align__(16) float g_combWsm[H_ * D_];
__device__ float g_bEnc[N4H];
__device__ float g_bDec[N4H];

// ============================ init / repack ============================
__global__ void init_kernel(const float* __restrict__ input) {
    int idx = blockIdx.x * blockDim.x + threadIdx.x;
    if (idx < B_ * H_) {
        g_hA[idx] = 0.f; g_c[idx] = 0.f;
        g_hAh[idx] = __float2bfloat16(0.f); g_hAl[idx] = __float2bfloat16(0.f);
    }
    if (idx < B_ * D_) {
        int b = idx >> 2, d = idx & 3;
        g_xA[idx] = input[b * (L_ * D_) + (L_ - 1) * D_ + d];
    }
}

__global__ void repack_kernel(const float* __restrict__ encHH, const float* __restrict__ encIH,
                              const float* __restrict__ decIH, const float* __restrict__ decHH,
                              const float* __restrict__ combW,
                              const float* __restrict__ eb1, const float* __restrict__ eb2,
                              const float* __restrict__ db1, const float* __restrict__ db2)
{
    int n = blockIdx.x;                          // new row index 0..2047
    int w = n & 15, chunk = n >> 4;
    int gate = ((w >> 3) << 1) | (w & 1);
    int u = chunk * 4 + ((w >> 1) & 3);
    int src = gate * H_ + u;
    for (int k = threadIdx.x; k < H_; k += blockDim.x) {
        bf16 hi, lo;
        bsplit(encHH[src * H_ + k], hi, lo);
        g_WencHHh[n * H_ + k] = hi; g_WencHHl[n * H_ + k] = lo;
        bsplit(decIH[src * H_ + k], hi, lo);
        g_WdecIHh[n * H_ + k] = hi; g_WdecIHl[n * H_ + k] = lo;
        bsplit(decHH[src * H_ + k], hi, lo);
        g_WdecHHh[n * H_ + k] = hi; g_WdecHHl[n * H_ + k] = lo;
        if (n < H_) {
            bsplit(combW[n * CW + D_ + k], hi, lo);      // natural order for comb
            g_combWh[n * H_ + k] = hi; g_combWl[n * H_ + k] = lo;
        }
    }
    if (threadIdx.x < D_) {
        g_WencIH[n * D_ + threadIdx.x] = encIH[src * D_ + threadIdx.x];
        if (n < H_) g_combWsm[n * D_ + threadIdx.x] = combW[n * CW + threadIdx.x];
    }
    if (threadIdx.x == 0) {
        g_bEnc[n] = eb1[src] + eb2[src];
        g_bDec[n] = db1[src] + db2[src];
    }
}

// ============================ HMMA GEMM (+fused epilogue) ============================
// C[64x128] = A(hi/lo bf16, 64xK) @ W(hi/lo bf16, 128xK)^T via 3x mma.sync.m16n8k16
// per k16 (hi*hi + hi*lo + lo*hi), fp32 accum. 8 warps, warp tile 32m x 32n.
// BK=32, cp.async 2-stage double buffer, 80B-padded rows.
// 3 blocks/SM (65KB smem, <=85 regs) -> 24 warps/SM for latency hiding.

#define ROW_B   80
#define A_OFF   0                         // Ah rows 0..63
#define AL_OFF  (64 * ROW_B)              // Al rows 64..127
#define BH_OFF  (128 * ROW_B)             // Bh rows 128..255
#define BL_OFF  (256 * ROW_B)             // Bl rows 256..383
#define STAGE_B (384 * ROW_B)             // 30720 bytes per stage
#define SM_BIAS (2 * STAGE_B)             // 61440
#define SM_XS   (SM_BIAS + 512)           // 64 x 4 floats
#define SM_WS   (SM_XS + 1024)            // 128 x 4 floats
#define SMEM_TOTAL (SM_WS + 2048)         // 65024 bytes

template<int NPASS, bool HAS_SMALL, bool LSTM_EPI, bool WRITE_ENC>
__global__ void __launch_bounds__(256, 3)
mma_kernel(const bf16* __restrict__ A0h, const bf16* __restrict__ A0l,
           const bf16* __restrict__ B0h, const bf16* __restrict__ B0l,
           const bf16* __restrict__ A1h, const bf16* __restrict__ A1l,
           const bf16* __restrict__ B1h, const bf16* __restrict__ B1l,
           const float* __restrict__ Asm, int ldasm, const float* __restrict__ Wsm,
           const float* __restrict__ bias,
           const float* __restrict__ c_in, float* __restrict__ c_out,
           float* __restrict__ h_out, bf16* __restrict__ hh_out, bf16* __restrict__ hl_out,
           float* __restrict__ enc_slot)
{
    extern __shared__ char smem[];
    const uint32_t sb = smem_u32(smem);
    const int tid = threadIdx.x;
    const int wid = tid >> 5, lane = tid & 31;
    const int warp_m = wid & 1, warp_n = wid >> 1;    // 2 x 4 warp grid, 32x32 each
    const int lane8 = lane & 7, sel = lane >> 3;
    const int gID = lane >> 2, tig = lane & 3;
    const int bn = blockIdx.x * 128;
    const int bm = blockIdx.y * 64;

    float* sbias = (float*)(smem + SM_BIAS);
    float* xs    = (float*)(smem + SM_XS);
    float* ws    = (float*)(smem + SM_WS);

    if (tid < 128) sbias[tid] = bias[bn + tid];
    if (HAS_SMALL) {
        if (tid < 64) {
            const float* xr = Asm + (size_t)(bm + tid) * ldasm;
            xs[tid * 4 + 0] = __ldcg(xr + 0); xs[tid * 4 + 1] = __ldcg(xr + 1);
            xs[tid * 4 + 2] = __ldcg(xr + 2); xs[tid * 4 + 3] = __ldcg(xr + 3);
        } else if (tid < 192) {
            int r = tid - 64;
            float4 v = *reinterpret_cast<const float4*>(&Wsm[(bn + r) * 4]);
            ws[r * 4 + 0] = v.x; ws[r * 4 + 1] = v.y; ws[r * 4 + 2] = v.z; ws[r * 4 + 3] = v.w;
        }
    }

    float acc[2][4][4];
    #pragma unroll
    for (int mt = 0; mt < 2; mt++)
        #pragma unroll
        for (int nt = 0; nt < 4; nt++)
            #pragma unroll
            for (int c = 0; c < 4; c++) acc[mt][nt][c] = 0.f;

    const int NS = NPASS * 16;

    auto load_stage = [&](int buf, int s) {
        const bool p1 = (NPASS == 2) && (s >= 16);
        const bf16* Ah = p1 ? A1h : A0h;
        const bf16* Al = p1 ? A1l : A0l;
        const bf16* Bh = p1 ? B1h : B0h;
        const bf16* Bl = p1 ? B1l : B0l;
        const int k0 = (s & 15) * 32;
        const uint32_t tb = sb + buf * STAGE_B;
        #pragma unroll
        for (int j = 0; j < 6; j++) {
            const int sIdx = j * 256 + tid;
            const int row = sIdx >> 2, seg = sIdx & 3;      // row uniform-range per j
            const bf16* g; int grow;
            if (row < 64)       { g = Ah; grow = bm + row; }
            else if (row < 128) { g = Al; grow = bm + row - 64; }
            else if (row < 256) { g = Bh; grow = bn + row - 128; }
            else                { g = Bl; grow = bn + row - 256; }
            const bf16* gp = g + (size_t)grow * H_ + k0 + seg * 8;
            const uint32_t sa = tb + row * ROW_B + seg * 16;
            if (j < 2) { CP_ASYNC_CG16(sa, gp); }   // A operands (dynamic)
            else       { CP_ASYNC_CA16(sa, gp); }   // B operands (static weights)
        }
        CP_COMMIT();
    };

    auto compute = [&](int buf) {
        const uint32_t tb = sb + buf * STAGE_B;
        #pragma unroll
        for (int kq = 0; kq < 2; kq++) {
            const int kk = kq * 16;
            const int kcol = (kk + ((sel >> 1) << 3)) * 2;
            uint32_t ah[2][4], al[2][4];
            #pragma unroll
            for (int mt = 0; mt < 2; mt++) {
                const int ar = warp_m * 32 + mt * 16 + ((sel & 1) << 3) + lane8;
                uint32_t ra = tb + (uint32_t)(ar * ROW_B) + kcol;
                ldsm4(ah[mt], ra + A_OFF);
                ldsm4(al[mt], ra + AL_OFF);
            }
            const int kcolb = (kk + ((sel & 1) << 3)) * 2;
            uint32_t bh[2][4], bl[2][4];
            #pragma unroll
            for (int p = 0; p < 2; p++) {
                const int br = warp_n * 32 + (2 * p + (sel >> 1)) * 8 + lane8;
                uint32_t rb = tb + (uint32_t)(br * ROW_B) + kcolb;
                ldsm4(bh[p], rb + BH_OFF);
                ldsm4(bl[p], rb + BL_OFF);
            }
            #pragma unroll
            for (int mt = 0; mt < 2; mt++)
                #pragma unroll
                for (int p = 0; p < 2; p++) {
                    mma16816(acc[mt][2 * p],     ah[mt], bh[p]);
                    mma16816(acc[mt][2 * p + 1], ah[mt], bh[p] + 2);
                    mma16816(acc[mt][2 * p],     ah[mt], bl[p]);
                    mma16816(acc[mt][2 * p + 1], ah[mt], bl[p] + 2);
                    mma16816(acc[mt][2 * p],     al[mt], bh[p]);
                    mma16816(acc[mt][2 * p + 1], al[mt], bh[p] + 2);
                }
        }
    };

    load_stage(0, 0);
    #pragma unroll 1
    for (int s = 0; s < NS; s++) {
        if (s + 1 < NS) {
            load_stage((s + 1) & 1, s + 1);
            asm volatile("cp.async.wait_group 1;" ::: "memory");
        } else {
            asm volatile("cp.async.wait_group 0;" ::: "memory");
        }
        __syncthreads();
        compute(s & 1);
        __syncthreads();
    }

    // -------------------- epilogue --------------------
    if (LSTM_EPI) {
        #pragma unroll
        for (int mt = 0; mt < 2; mt++) {
            #pragma unroll
            for (int rh = 0; rh < 2; rh++) {           // C-fragment row half (+0 / +8)
                const int rl = warp_m * 32 + mt * 16 + gID + rh * 8;
                const int grow = bm + rl;
                const int ci = rh * 2;
                float x0 = 0.f, x1 = 0.f, x2 = 0.f, x3 = 0.f;
                if (HAS_SMALL) {
                    const float* xr = xs + rl * 4;
                    x0 = xr[0]; x1 = xr[1]; x2 = xr[2]; x3 = xr[3];
                }
                #pragma unroll
                for (int k = 0; k < 2; k++) {
                    const int ni = warp_n * 32 + k * 16 + 2 * tig;   // local col of gate i
                    float pi = acc[mt][2 * k][ci]     + sbias[ni];
                    float pf = acc[mt][2 * k][ci + 1] + sbias[ni + 1];
                    float pg = acc[mt][2 * k + 1][ci]     + sbias[ni + 8];
                    float po = acc[mt][2 * k + 1][ci + 1] + sbias[ni + 9];
                    if (HAS_SMALL) {
                        const float* wi = ws + ni * 4;
                        const float* wf = ws + (ni + 1) * 4;
                        const float* wg = ws + (ni + 8) * 4;
                        const float* wo = ws + (ni + 9) * 4;
                        pi += x0 * wi[0] + x1 * wi[1] + x2 * wi[2] + x3 * wi[3];
                        pf += x0 * wf[0] + x1 * wf[1] + x2 * wf[2] + x3 * wf[3];
                        pg += x0 * wg[0] + x1 * wg[1] + x2 * wg[2] + x3 * wg[3];
                        po += x0 * wo[0] + x1 * wo[1] + x2 * wo[2] + x3 * wo[3];
                    }
                    const int u = (bn >> 2) + warp_n * 8 + k * 4 + tig;
                    const int idx = grow * H_ + u;
                    float cold = c_in[idx];
                    float cn = sigf(pf) * cold + sigf(pi) * tanhf(pg);
                    float hn = sigf(po) * tanhf(cn);
                    c_out[idx] = cn;
                    h_out[idx] = hn;
                    bf16 hh, hl; bsplit(hn, hh, hl);
                    hh_out[idx] = hh; hl_out[idx] = hl;
                    if (WRITE_ENC) enc_slot[grow * (L_ * H_) + u] = hn;
                }
            }
        }
    } else {
        #pragma unroll
        for (int mt = 0; mt < 2; mt++) {
            #pragma unroll
            for (int c = 0; c < 4; c++) {
                const int rl = warp_m * 32 + mt * 16 + gID + (c >> 1) * 8;
                const int grow = bm + rl;
                float x0 = 0.f, x1 = 0.f, x2 = 0.f, x3 = 0.f;
                if (HAS_SMALL) {
                    const float* xr = xs + rl * 4;
                    x0 = xr[0]; x1 = xr[1]; x2 = xr[2]; x3 = xr[3];
                }
                #pragma unroll
                for (int nt = 0; nt < 4; nt++) {
                    const int nl = warp_n * 32 + nt * 8 + 2 * tig + (c & 1);
                    float v = acc[mt][nt][c] + sbias[nl];
                    if (HAS_SMALL) {
                        const float* w = ws + nl * 4;
                        v += x0 * w[0] + x1 * w[1] + x2 * w[2] + x3 * w[3];
                    }
                    v = fmaxf(v, 0.f);
                    const int idx = grow * H_ + bn + nl;
                    bf16 hh, hl; bsplit(v, hh, hl);
                    hh_out[idx] = hh; hl_out[idx] = hl;
                }
            }
        }
    }
}

// ============================ attention (fp32) ============================
// h_r[b,k] = h[2k + (b>=512), b & 511]  (reference's reshape/transpose quirk)
__global__ void __launch_bounds__(256)
attn_kernel(const float* __restrict__ x, const float* __restrict__ h,
            const float* __restrict__ attn_W, const float* __restrict__ attn_b,
            const float* __restrict__ enc, bf16* __restrict__ outH, bf16* __restrict__ outL)
{
    __shared__ float v[H_ + D_];
    __shared__ float wts[64];
    const int b = blockIdx.x;
    const int tid = threadIdx.x;

    if (tid < D_) v[tid] = x[b * D_ + tid];
    {
        int brow = b >> 9, bcol = b & 511;
        for (int k = tid; k < H_; k += 256)
            v[D_ + k] = h[(2 * k + brow) * H_ + bcol];
    }
    __syncthreads();

    const int warp = tid >> 5, lane = tid & 31;
    for (int l = warp; l < L_; l += 8) {
        const float* wrow = attn_W + l * (H_ + D_);
        float s = 0.f;
        for (int k = lane; k < H_ + D_; k += 32) s += v[k] * wrow[k];
        #pragma unroll
        for (int off = 16; off; off >>= 1) s += __shfl_xor_sync(0xffffffffu, s, off);
        if (lane == 0) wts[l] = s + attn_b[l];
    }
    __syncthreads();

    if (tid < 32) {
        float v1 = (tid < L_) ? wts[tid] : -1e30f;
        float v2 = (tid + 32 < L_) ? wts[tid + 32] : -1e30f;
        float m = fmaxf(v1, v2);
        #pragma unroll
        for (int off = 16; off; off >>= 1) m = fmaxf(m, __shfl_xor_sync(0xffffffffu, m, off));
        float e1 = (tid < L_) ? __expf(v1 - m) : 0.f;
        float e2 = (tid + 32 < L_) ? __expf(v2 - m) : 0.f;
        float s = e1 + e2;
        #pragma unroll
        for (int off = 16; off; off >>= 1) s += __shfl_xor_sync(0xffffffffu, s, off);
        float inv = 1.f / s;
        if (tid < L_) wts[tid] = e1 * inv;
        if (tid + 32 < L_) wts[tid + 32] = e2 * inv;
    }
    __syncthreads();

    const float* e = enc + (size_t)b * (L_ * H_);
    for (int j = tid; j < H_; j += 256) {
        float s = 0.f;
        #pragma unroll
        for (int l = 0; l < L_; l++) s += wts[l] * e[l * H_ + j];
        bf16 hi, lo; bsplit(s, hi, lo);
        outH[b * H_ + j] = hi; outL[b * H_ + j] = lo;
    }
}

// ============================ pred ============================
__global__ void pred_kernel(const float* __restrict__ h, const float* __restrict__ out_W,
                            const float* __restrict__ out_b, float* __restrict__ out,
                            int t, float* __restrict__ x_next)
{
    const int b = blockIdx.x;
    const int warp = threadIdx.x >> 5, lane = threadIdx.x & 31;
    const float* hr = h + b * H_;
    const float* w = out_W + warp * H_;
    float s = 0.f;
    #pragma unroll
    for (int k = lane; k < H_; k += 32) s += hr[k] * w[k];
    #pragma unroll
    for (int off = 16; off; off >>= 1) s += __shfl_xor_sync(0xffffffffu, s, off);
    if (lane == 0) {
        float p = s + out_b[warp];
        out[(b * T_ + t) * D_ + warp] = p;
        x_next[b * D_ + warp] = p;
    }
}

// ============================ launch ============================
extern "C" void kernel_launch(void* const* d_in, const int* in_sizes, int n_in,
                              void* d_out, int out_size)
{
    int base = (n_in >= 16 && in_sizes[1] == 1) ? 2 : 1;

    const float* input    = (const float*)d_in[0];
    const float* enc_W_ih = (const float*)d_in[base + 0];
    const float* enc_W_hh = (const float*)d_in[base + 1];
    const float* enc_b_ih = (const float*)d_in[base + 2];
    const float* enc_b_hh = (const float*)d_in[base + 3];
    const float* attn_W   = (const float*)d_in[base + 4];
    const float* attn_b   = (const float*)d_in[base + 5];
    const float* comb_W   = (const float*)d_in[base + 6];
    const float* comb_b   = (const float*)d_in[base + 7];
    const float* dec_W_ih = (const float*)d_in[base + 8];
    const float* dec_W_hh = (const float*)d_in[base + 9];
    const float* dec_b_ih = (const float*)d_in[base + 10];
    const float* dec_b_hh = (const float*)d_in[base + 11];
    const float* out_W    = (const float*)d_in[base + 12];
    const float* out_b    = (const float*)d_in[base + 13];
    float* outp = (float*)d_out;

    float *hA, *hB, *c, *enc, *xA, *xB, *WencIH, *combWsm, *bEnc, *bDec;
    bf16 *hAh, *hAl, *hBh, *hBl, *attnH, *attnL, *combH, *combL;
    bf16 *WencHHh, *WencHHl, *WdecIHh, *WdecIHl, *WdecHHh, *WdecHHl, *combWh, *combWl;
    cudaGetSymbolAddress((void**)&hA, g_hA);
    cudaGetSymbolAddress((void**)&hB, g_hB);
    cudaGetSymbolAddress((void**)&hAh, g_hAh);
    cudaGetSymbolAddress((void**)&hAl, g_hAl);
    cudaGetSymbolAddress((void**)&hBh, g_hBh);
    cudaGetSymbolAddress((void**)&hBl, g_hBl);
    cudaGetSymbolAddress((void**)&c, g_c);
    cudaGetSymbolAddress((void**)&enc, g_enc);
    cudaGetSymbolAddress((void**)&attnH, g_attnH);
    cudaGetSymbolAddress((void**)&attnL, g_attnL);
    cudaGetSymbolAddress((void**)&combH, g_combH);
    cudaGetSymbolAddress((void**)&combL, g_combL);
    cudaGetSymbolAddress((void**)&xA, g_xA);
    cudaGetSymbolAddress((void**)&xB, g_xB);
    cudaGetSymbolAddress((void**)&WencHHh, g_WencHHh);
    cudaGetSymbolAddress((void**)&WencHHl, g_WencHHl);
    cudaGetSymbolAddress((void**)&WdecIHh, g_WdecIHh);
    cudaGetSymbolAddress((void**)&WdecIHl, g_WdecIHl);
    cudaGetSymbolAddress((void**)&WdecHHh, g_WdecHHh);
    cudaGetSymbolAddress((void**)&WdecHHl, g_WdecHHl);
    cudaGetSymbolAddress((void**)&WencIH, g_WencIH);
    cudaGetSymbolAddress((void**)&combWh, g_combWh);
    cudaGetSymbolAddress((void**)&combWl, g_combWl);
    cudaGetSymbolAddress((void**)&combWsm, g_combWsm);
    cudaGetSymbolAddress((void**)&bEnc, g_bEnc);
    cudaGetSymbolAddress((void**)&bDec, g_bDec);

    cudaFuncSetAttribute(mma_kernel<1, true, true, true>,
                         cudaFuncAttributeMaxDynamicSharedMemorySize, SMEM_TOTAL);
    cudaFuncSetAttribute(mma_kernel<1, true, false, false>,
                         cudaFuncAttributeMaxDynamicSharedMemorySize, SMEM_TOTAL);
    cudaFuncSetAttribute(mma_kernel<2, false, true, false>,
                         cudaFuncAttributeMaxDynamicSharedMemorySize, SMEM_TOTAL);

    init_kernel<<<(B_ * H_ + 255) / 256, 256>>>(input);
    repack_kernel<<<N4H, 256>>>(enc_W_hh, enc_W_ih, dec_W_ih, dec_W_hh, comb_W,
                                enc_b_ih, enc_b_hh, dec_b_ih, dec_b_hh);

    const dim3 grid_gates(N4H / 128, B_ / 64);   // 16 x 16 = 256 blocks
    const dim3 grid_comb(H_ / 128, B_ / 64);     // 4 x 16 = 64 blocks

    // ---------------- encoder ----------------
    float *h_in = hA, *h_out = hB;
    bf16 *hih = hAh, *hil = hAl, *hoh = hBh, *hol = hBl;
    for (int t = 0; t < L_; t++) {
        mma_kernel<1, true, true, true><<<grid_gates, 256, SMEM_TOTAL>>>(
            hih, hil, WencHHh, WencHHl,
            nullptr, nullptr, nullptr, nullptr,
            input + t * D_, L_ * D_, WencIH,
            bEnc, c, c, h_out, hoh, hol, enc + t * H_);
        { float* tp = h_in; h_in = h_out; h_out = tp; }
        { bf16* tp = hih; hih = hoh; hoh = tp; tp = hil; hil = hol; hol = tp; }
    }

    // ---------------- decoder ----------------
    float *x_in = xA, *x_out = xB;
    for (int t = 0; t < T_; t++) {
        attn_kernel<<<B_, 256>>>(x_in, h_in, attn_W, attn_b, enc, attnH, attnL);
        mma_kernel<1, true, false, false><<<grid_comb, 256, SMEM_TOTAL>>>(
            attnH, attnL, combWh, combWl,
            nullptr, nullptr, nullptr, nullptr,
            x_in, D_, combWsm,
            comb_b, nullptr, nullptr, nullptr, combH, combL, nullptr);
        mma_kernel<2, false, true, false><<<grid_gates, 256, SMEM_TOTAL>>>(
            combH, combL, WdecIHh, WdecIHl,
            hih, hil, WdecHHh, WdecHHl,
            nullptr, 0, nullptr,
            bDec, c, c, h_out, hoh, hol, nullptr);
        pred_kernel<<<B_, 128>>>(h_out, out_W, out_b, outp, t, x_out);
        { float* tp = h_in; h_in = h_out; h_out = tp; }
        { bf16* tp = hih; hih = hoh; hoh = tp; tp = hil; hil = hol; hol = tp; }
        { float* tp = x_in; x_in = x_out; x_out = tp; }
    }
}

// round 14
// speedup vs baseline: 1.0316x; 1.0316x over previous
#include <cuda_runtime.h>
#include <cuda_bf16.h>
#include <math.h>
#include <stdint.h>

#define B_  1024
#define L_  50
#define D_  4
#define H_  512
#define T_  30
#define N4H 2048
#define CW  516

typedef __nv_bfloat16 bf16;

// ===================== base-ISA PTX helpers (sm_80+ features only) =====================
__device__ __forceinline__ uint32_t smem_u32(const void* p) {
    uint32_t a;
    asm("{ .reg .u64 t; cvta.to.shared.u64 t, %1; cvt.u32.u64 %0, t; }" : "=r"(a) : "l"(p));
    return a;
}
__device__ __forceinline__ void mma16816(float* d, const uint32_t* a, const uint32_t* b) {
    asm volatile(
        "mma.sync.aligned.m16n8k16.row.col.f32.bf16.bf16.f32 "
        "{%0,%1,%2,%3}, {%4,%5,%6,%7}, {%8,%9}, {%0,%1,%2,%3};"
        : "+f"(d[0]), "+f"(d[1]), "+f"(d[2]), "+f"(d[3])
        : "r"(a[0]), "r"(a[1]), "r"(a[2]), "r"(a[3]), "r"(b[0]), "r"(b[1]));
}
__device__ __forceinline__ void ldsm4(uint32_t* r, uint32_t addr) {
    asm volatile("ldmatrix.sync.aligned.m8n8.x4.shared.b16 {%0,%1,%2,%3}, [%4];"
        : "=r"(r[0]), "=r"(r[1]), "=r"(r[2]), "=r"(r[3]) : "r"(addr));
}
#define CP_ASYNC16(sa, gp) \
    asm volatile("cp.async.ca.shared.global [%0], [%1], 16;" :: "r"(sa), "l"(gp) : "memory")
#define CP_COMMIT() asm volatile("cp.async.commit_group;" ::: "memory")

__device__ __forceinline__ float sigf(float x) { return 1.f / (1.f + __expf(-x)); }
__device__ __forceinline__ void bsplit(float v, bf16& hi, bf16& lo) {
    hi = __float2bfloat16(v);
    lo = __float2bfloat16(v - __bfloat162float(hi));
}

// ============================ persistent device state ============================
__device__ __align__(16) float g_hA[B_ * H_];
__device__ __align__(16) float g_hB[B_ * H_];
__device__ __align__(16) bf16  g_hAh[B_ * H_];
__device__ __align__(16) bf16  g_hAl[B_ * H_];
__device__ __align__(16) bf16  g_hBh[B_ * H_];
__device__ __align__(16) bf16  g_hBl[B_ * H_];
__device__ __align__(16) float g_c[B_ * H_];
__device__ __align__(16) float g_enc[B_ * L_ * H_];
__device__ __align__(16) bf16  g_attnH[B_ * H_];
__device__ __align__(16) bf16  g_attnL[B_ * H_];
__device__ __align__(16) bf16  g_combH[B_ * H_];
__device__ __align__(16) bf16  g_combL[B_ * H_];
__device__ __align__(16) float g_xA[B_ * D_];
__device__ __align__(16) float g_xB[B_ * D_];
// gate-permuted weights for fused LSTM epilogue:
// new col n: chunk=n>>4, w=n&15, gate=((w>>3)<<1)|(w&1), unit=chunk*4+((w>>1)&3)
__device__ __align__(16) bf16  g_WencHHh[N4H * H_];
__device__ __align__(16) bf16  g_WencHHl[N4H * H_];
__device__ __align__(16) bf16  g_WdecIHh[N4H * H_];
__device__ __align__(16) bf16  g_WdecIHl[N4H * H_];
__device__ __align__(16) bf16  g_WdecHHh[N4H * H_];
__device__ __align__(16) bf16  g_WdecHHl[N4H * H_];
__device__ __align__(16) float g_WencIH[N4H * D_];
__device__ __align__(16) bf16  g_combWh[H_ * H_];
__device__ __align__(16) bf16  g_combWl[H_ * H_];
__device__ __align__(16) float g_combWsm[H_ * D_];
__device__ float g_bEnc[N4H];
__device__ float g_bDec[N4H];

// ============================ init / repack ============================
__global__ void init_kernel(const float* __restrict__ input) {
    int idx = blockIdx.x * blockDim.x + threadIdx.x;
    if (idx < B_ * H_) {
        g_hA[idx] = 0.f; g_c[idx] = 0.f;
        g_hAh[idx] = __float2bfloat16(0.f); g_hAl[idx] = __float2bfloat16(0.f);
    }
    if (idx < B_ * D_) {
        int b = idx >> 2, d = idx & 3;
        g_xA[idx] = input[b * (L_ * D_) + (L_ - 1) * D_ + d];
    }
}

__global__ void repack_kernel(const float* __restrict__ encHH, const float* __restrict__ encIH,
                              const float* __restrict__ decIH, const float* __restrict__ decHH,
                              const float* __restrict__ combW,
                              const float* __restrict__ eb1, const float* __restrict__ eb2,
                              const float* __restrict__ db1, const float* __restrict__ db2)
{
    int n = blockIdx.x;                          // new row index 0..2047
    int w = n & 15, chunk = n >> 4;
    int gate = ((w >> 3) << 1) | (w & 1);
    int u = chunk * 4 + ((w >> 1) & 3);
    int src = gate * H_ + u;
    for (int k = threadIdx.x; k < H_; k += blockDim.x) {
        bf16 hi, lo;
        bsplit(encHH[src * H_ + k], hi, lo);
        g_WencHHh[n * H_ + k] = hi; g_WencHHl[n * H_ + k] = lo;
        bsplit(decIH[src * H_ + k], hi, lo);
        g_WdecIHh[n * H_ + k] = hi; g_WdecIHl[n * H_ + k] = lo;
        bsplit(decHH[src * H_ + k], hi, lo);
        g_WdecHHh[n * H_ + k] = hi; g_WdecHHl[n * H_ + k] = lo;
        if (n < H_) {
            bsplit(combW[n * CW + D_ + k], hi, lo);      // natural order for comb
            g_combWh[n * H_ + k] = hi; g_combWl[n * H_ + k] = lo;
        }
    }
    if (threadIdx.x < D_) {
        g_WencIH[n * D_ + threadIdx.x] = encIH[src * D_ + threadIdx.x];
        if (n < H_) g_combWsm[n * D_ + threadIdx.x] = combW[n * CW + threadIdx.x];
    }
    if (threadIdx.x == 0) {
        g_bEnc[n] = eb1[src] + eb2[src];
        g_bDec[n] = db1[src] + db2[src];
    }
}

// ============================ HMMA GEMM (+fused epilogue) ============================
// C[64x64] = A(hi/lo bf16, 64xK) @ W(hi/lo bf16, 64xK)^T via 3x mma.sync.m16n8k16
// per k16 (hi*hi + hi*lo + lo*hi), fp32 accum. 8 warps, warp tile 32m x 16n.
// BK=32, cp.async 3-stage ring (prefetch distance 2), 80B-padded rows.
// Small tiles -> 512-block grid -> ~3 blocks/SM resident (24 warps/SM).

#define ROW_B   80
#define A_OFF   0                         // Ah rows 0..63
#define AL_OFF  (64 * ROW_B)              // Al rows 64..127
#define BH_OFF  (128 * ROW_B)             // Bh rows 128..191
#define BL_OFF  (192 * ROW_B)             // Bl rows 192..255
#define STAGE_B (256 * ROW_B)             // 20480 bytes per stage
#define SM_BIAS (3 * STAGE_B)             // 61440
#define SM_XS   (SM_BIAS + 512)           // 64 x 4 floats
#define SM_WS   (SM_XS + 1024)            // 64 x 4 floats
#define SMEM_TOTAL (SM_WS + 1024)         // 64000 bytes

template<int NPASS, bool HAS_SMALL, bool LSTM_EPI, bool WRITE_ENC>
__global__ void __launch_bounds__(256, 3)
mma_kernel(const bf16* __restrict__ A0h, const bf16* __restrict__ A0l,
           const bf16* __restrict__ B0h, const bf16* __restrict__ B0l,
           const bf16* __restrict__ A1h, const bf16* __restrict__ A1l,
           const bf16* __restrict__ B1h, const bf16* __restrict__ B1l,
           const float* __restrict__ Asm, int ldasm, const float* __restrict__ Wsm,
           const float* __restrict__ bias,
           const float* __restrict__ c_in, float* __restrict__ c_out,
           float* __restrict__ h_out, bf16* __restrict__ hh_out, bf16* __restrict__ hl_out,
           float* __restrict__ enc_slot)
{
    extern __shared__ char smem[];
    const uint32_t sb = smem_u32(smem);
    const int tid = threadIdx.x;
    const int wid = tid >> 5, lane = tid & 31;
    const int warp_m = wid & 1, warp_n = wid >> 1;    // 2 x 4 warp grid, 32m x 16n each
    const int lane8 = lane & 7, sel = lane >> 3;
    const int gID = lane >> 2, tig = lane & 3;
    const int bn = blockIdx.x * 64;
    const int bm = blockIdx.y * 64;

    float* sbias = (float*)(smem + SM_BIAS);
    float* xs    = (float*)(smem + SM_XS);
    float* ws    = (float*)(smem + SM_WS);

    if (tid < 64) sbias[tid] = bias[bn + tid];
    if (HAS_SMALL) {
        if (tid >= 64 && tid < 128) {
            int r = tid - 64;
            const float* xr = Asm + (size_t)(bm + r) * ldasm;
            xs[r * 4 + 0] = xr[0]; xs[r * 4 + 1] = xr[1];
            xs[r * 4 + 2] = xr[2]; xs[r * 4 + 3] = xr[3];
        } else if (tid >= 128 && tid < 192) {
            int r = tid - 128;
            float4 v = *reinterpret_cast<const float4*>(&Wsm[(bn + r) * 4]);
            ws[r * 4 + 0] = v.x; ws[r * 4 + 1] = v.y; ws[r * 4 + 2] = v.z; ws[r * 4 + 3] = v.w;
        }
    }

    float acc[2][2][4];
    #pragma unroll
    for (int mt = 0; mt < 2; mt++)
        #pragma unroll
        for (int nt = 0; nt < 2; nt++)
            #pragma unroll
            for (int c = 0; c < 4; c++) acc[mt][nt][c] = 0.f;

    const int NS = NPASS * 16;

    auto load_stage = [&](int buf, int s) {
        const bool p1 = (NPASS == 2) && (s >= 16);
        const bf16* Ah = p1 ? A1h : A0h;
        const bf16* Al = p1 ? A1l : A0l;
        const bf16* Bh = p1 ? B1h : B0h;
        const bf16* Bl = p1 ? B1l : B0l;
        const int k0 = (s & 15) * 32;
        const uint32_t tb = sb + buf * STAGE_B;
        #pragma unroll
        for (int j = 0; j < 4; j++) {
            const int sIdx = j * 256 + tid;
            const int row = sIdx >> 2, seg = sIdx & 3;      // 64-row uniform range per j
            const bf16* g; int grow;
            if (row < 64)       { g = Ah; grow = bm + row; }
            else if (row < 128) { g = Al; grow = bm + row - 64; }
            else if (row < 192) { g = Bh; grow = bn + row - 128; }
            else                { g = Bl; grow = bn + row - 192; }
            const bf16* gp = g + (size_t)grow * H_ + k0 + seg * 8;
            CP_ASYNC16(tb + row * ROW_B + seg * 16, gp);
        }
        CP_COMMIT();
    };

    auto compute = [&](int buf) {
        const uint32_t tb = sb + buf * STAGE_B;
        #pragma unroll
        for (int kq = 0; kq < 2; kq++) {
            const int kk = kq * 16;
            const int kcol = (kk + ((sel >> 1) << 3)) * 2;
            uint32_t ah[2][4], al[2][4];
            #pragma unroll
            for (int mt = 0; mt < 2; mt++) {
                const int ar = warp_m * 32 + mt * 16 + ((sel & 1) << 3) + lane8;
                uint32_t ra = tb + (uint32_t)(ar * ROW_B) + kcol;
                ldsm4(ah[mt], ra + A_OFF);
                ldsm4(al[mt], ra + AL_OFF);
            }
            const int kcolb = (kk + ((sel & 1) << 3)) * 2;
            uint32_t bh[4], bl[4];
            {
                const int br = warp_n * 16 + ((sel >> 1) << 3) + lane8;
                uint32_t rb = tb + (uint32_t)(br * ROW_B) + kcolb;
                ldsm4(bh, rb + BH_OFF);
                ldsm4(bl, rb + BL_OFF);
            }
            #pragma unroll
            for (int mt = 0; mt < 2; mt++) {
                mma16816(acc[mt][0], ah[mt], bh);
                mma16816(acc[mt][1], ah[mt], bh + 2);
                mma16816(acc[mt][0], ah[mt], bl);
                mma16816(acc[mt][1], ah[mt], bl + 2);
                mma16816(acc[mt][0], al[mt], bh);
                mma16816(acc[mt][1], al[mt], bh + 2);
            }
        }
    };

    load_stage(0, 0);
    if (NS > 1) load_stage(1, 1);
    #pragma unroll 1
    for (int s = 0; s < NS; s++) {
        if (s + 2 < NS) {
            load_stage((s + 2) % 3, s + 2);
            asm volatile("cp.async.wait_group 2;" ::: "memory");
        } else if (s + 1 < NS) {
            asm volatile("cp.async.wait_group 1;" ::: "memory");
        } else {
            asm volatile("cp.async.wait_group 0;" ::: "memory");
        }
        __syncthreads();
        compute(s % 3);
        __syncthreads();
    }

    // -------------------- epilogue --------------------
    if (LSTM_EPI) {
        #pragma unroll
        for (int mt = 0; mt < 2; mt++) {
            #pragma unroll
            for (int rh = 0; rh < 2; rh++) {           // C-fragment row half (+0 / +8)
                const int rl = warp_m * 32 + mt * 16 + gID + rh * 8;
                const int grow = bm + rl;
                const int ci = rh * 2;
                float x0 = 0.f, x1 = 0.f, x2 = 0.f, x3 = 0.f;
                if (HAS_SMALL) {
                    const float* xr = xs + rl * 4;
                    x0 = xr[0]; x1 = xr[1]; x2 = xr[2]; x3 = xr[3];
                }
                const int ni = warp_n * 16 + 2 * tig;      // local col of gate i
                float pi = acc[mt][0][ci]     + sbias[ni];
                float pf = acc[mt][0][ci + 1] + sbias[ni + 1];
                float pg = acc[mt][1][ci]     + sbias[ni + 8];
                float po = acc[mt][1][ci + 1] + sbias[ni + 9];
                if (HAS_SMALL) {
                    const float* wi = ws + ni * 4;
                    const float* wf = ws + (ni + 1) * 4;
                    const float* wg = ws + (ni + 8) * 4;
                    const float* wo = ws + (ni + 9) * 4;
                    pi += x0 * wi[0] + x1 * wi[1] + x2 * wi[2] + x3 * wi[3];
                    pf += x0 * wf[0] + x1 * wf[1] + x2 * wf[2] + x3 * wf[3];
                    pg += x0 * wg[0] + x1 * wg[1] + x2 * wg[2] + x3 * wg[3];
                    po += x0 * wo[0] + x1 * wo[1] + x2 * wo[2] + x3 * wo[3];
                }
                const int u = (bn >> 2) + warp_n * 4 + tig;
                const int idx = grow * H_ + u;
                float cold = c_in[idx];
                float cn = sigf(pf) * cold + sigf(pi) * tanhf(pg);
                float hn = sigf(po) * tanhf(cn);
                c_out[idx] = cn;
                h_out[idx] = hn;
                bf16 hh, hl; bsplit(hn, hh, hl);
                hh_out[idx] = hh; hl_out[idx] = hl;
                if (WRITE_ENC) enc_slot[grow * (L_ * H_) + u] = hn;
            }
        }
    } else {
        #pragma unroll
        for (int mt = 0; mt < 2; mt++) {
            #pragma unroll
            for (int c = 0; c < 4; c++) {
                const int rl = warp_m * 32 + mt * 16 + gID + (c >> 1) * 8;
                const int grow = bm + rl;
                float x0 = 0.f, x1 = 0.f, x2 = 0.f, x3 = 0.f;
                if (HAS_SMALL) {
                    const float* xr = xs + rl * 4;
                    x0 = xr[0]; x1 = xr[1]; x2 = xr[2]; x3 = xr[3];
                }
                #pragma unroll
                for (int nt = 0; nt < 2; nt++) {
                    const int nl = warp_n * 16 + nt * 8 + 2 * tig + (c & 1);
                    float v = acc[mt][nt][c] + sbias[nl];
                    if (HAS_SMALL) {
                        const float* w = ws + nl * 4;
                        v += x0 * w[0] + x1 * w[1] + x2 * w[2] + x3 * w[3];
                    }
                    v = fmaxf(v, 0.f);
                    const int idx = grow * H_ + bn + nl;
                    bf16 hh, hl; bsplit(v, hh, hl);
                    hh_out[idx] = hh; hl_out[idx] = hl;
                }
            }
        }
    }
}

// ============================ attention (fp32) ============================
// h_r[b,k] = h[2k + (b>=512), b & 511]  (reference's reshape/transpose quirk)
__global__ void __launch_bounds__(256)
attn_kernel(const float* __restrict__ x, const float* __restrict__ h,
            const float* __restrict__ attn_W, const float* __restrict__ attn_b,
            const float* __restrict__ enc, bf16* __restrict__ outH, bf16* __restrict__ outL)
{
    __shared__ float v[H_ + D_];
    __shared__ float wts[64];
    const int b = blockIdx.x;
    const int tid = threadIdx.x;

    if (tid < D_) v[tid] = x[b * D_ + tid];
    {
        int brow = b >> 9, bcol = b & 511;
        for (int k = tid; k < H_; k += 256)
            v[D_ + k] = h[(2 * k + brow) * H_ + bcol];
    }
    __syncthreads();

    const int warp = tid >> 5, lane = tid & 31;
    for (int l = warp; l < L_; l += 8) {
        const float* wrow = attn_W + l * (H_ + D_);
        float s = 0.f;
        for (int k = lane; k < H_ + D_; k += 32) s += v[k] * wrow[k];
        #pragma unroll
        for (int off = 16; off; off >>= 1) s += __shfl_xor_sync(0xffffffffu, s, off);
        if (lane == 0) wts[l] = s + attn_b[l];
    }
    __syncthreads();

    if (tid < 32) {
        float v1 = (tid < L_) ? wts[tid] : -1e30f;
        float v2 = (tid + 32 < L_) ? wts[tid + 32] : -1e30f;
        float m = fmaxf(v1, v2);
        #pragma unroll
        for (int off = 16; off; off >>= 1) m = fmaxf(m, __shfl_xor_sync(0xffffffffu, m, off));
        float e1 = (tid < L_) ? __expf(v1 - m) : 0.f;
        float e2 = (tid + 32 < L_) ? __expf(v2 - m) : 0.f;
        float s = e1 + e2;
        #pragma unroll
        for (int off = 16; off; off >>= 1) s += __shfl_xor_sync(0xffffffffu, s, off);
        float inv = 1.f / s;
        if (tid < L_) wts[tid] = e1 * inv;
        if (tid + 32 < L_) wts[tid + 32] = e2 * inv;
    }
    __syncthreads();

    const float* e = enc + (size_t)b * (L_ * H_);
    for (int j = tid; j < H_; j += 256) {
        float s = 0.f;
        #pragma unroll
        for (int l = 0; l < L_; l++) s += wts[l] * e[l * H_ + j];
        bf16 hi, lo; bsplit(s, hi, lo);
        outH[b * H_ + j] = hi; outL[b * H_ + j] = lo;
    }
}

// ============================ pred ============================
__global__ void pred_kernel(const float* __restrict__ h, const float* __restrict__ out_W,
                            const float* __restrict__ out_b, float* __restrict__ out,
                            int t, float* __restrict__ x_next)
{
    const int b = blockIdx.x;
    const int warp = threadIdx.x >> 5, lane = threadIdx.x & 31;
    const float* hr = h + b * H_;
    const float* w = out_W + warp * H_;
    float s = 0.f;
    #pragma unroll
    for (int k = lane; k < H_; k += 32) s += hr[k] * w[k];
    #pragma unroll
    for (int off = 16; off; off >>= 1) s += __shfl_xor_sync(0xffffffffu, s, off);
    if (lane == 0) {
        float p = s + out_b[warp];
        out[(b * T_ + t) * D_ + warp] = p;
        x_next[b * D_ + warp] = p;
    }
}

// ============================ launch ============================
extern "C" void kernel_launch(void* const* d_in, const int* in_sizes, int n_in,
                              void* d_out, int out_size)
{
    int base = (n_in >= 16 && in_sizes[1] == 1) ? 2 : 1;

    const float* input    = (const float*)d_in[0];
    const float* enc_W_ih = (const float*)d_in[base + 0];
    const float* enc_W_hh = (const float*)d_in[base + 1];
    const float* enc_b_ih = (const float*)d_in[base + 2];
    const float* enc_b_hh = (const float*)d_in[base + 3];
    const float* attn_W   = (const float*)d_in[base + 4];
    const float* attn_b   = (const float*)d_in[base + 5];
    const float* comb_W   = (const float*)d_in[base + 6];
    const float* comb_b   = (const float*)d_in[base + 7];
    const float* dec_W_ih = (const float*)d_in[base + 8];
    const float* dec_W_hh = (const float*)d_in[base + 9];
    const float* dec_b_ih = (const float*)d_in[base + 10];
    const float* dec_b_hh = (const float*)d_in[base + 11];
    const float* out_W    = (const float*)d_in[base + 12];
    const float* out_b    = (const float*)d_in[base + 13];
    float* outp = (float*)d_out;

    float *hA, *hB, *c, *enc, *xA, *xB, *WencIH, *combWsm, *bEnc, *bDec;
    bf16 *hAh, *hAl, *hBh, *hBl, *attnH, *attnL, *combH, *combL;
    bf16 *WencHHh, *WencHHl, *WdecIHh, *WdecIHl, *WdecHHh, *WdecHHl, *combWh, *combWl;
    cudaGetSymbolAddress((void**)&hA, g_hA);
    cudaGetSymbolAddress((void**)&hB, g_hB);
    cudaGetSymbolAddress((void**)&hAh, g_hAh);
    cudaGetSymbolAddress((void**)&hAl, g_hAl);
    cudaGetSymbolAddress((void**)&hBh, g_hBh);
    cudaGetSymbolAddress((void**)&hBl, g_hBl);
    cudaGetSymbolAddress((void**)&c, g_c);
    cudaGetSymbolAddress((void**)&enc, g_enc);
    cudaGetSymbolAddress((void**)&attnH, g_attnH);
    cudaGetSymbolAddress((void**)&attnL, g_attnL);
    cudaGetSymbolAddress((void**)&combH, g_combH);
    cudaGetSymbolAddress((void**)&combL, g_combL);
    cudaGetSymbolAddress((void**)&xA, g_xA);
    cudaGetSymbolAddress((void**)&xB, g_xB);
    cudaGetSymbolAddress((void**)&WencHHh, g_WencHHh);
    cudaGetSymbolAddress((void**)&WencHHl, g_WencHHl);
    cudaGetSymbolAddress((void**)&WdecIHh, g_WdecIHh);
    cudaGetSymbolAddress((void**)&WdecIHl, g_WdecIHl);
    cudaGetSymbolAddress((void**)&WdecHHh, g_WdecHHh);
    cudaGetSymbolAddress((void**)&WdecHHl, g_WdecHHl);
    cudaGetSymbolAddress((void**)&WencIH, g_WencIH);
    cudaGetSymbolAddress((void**)&combWh, g_combWh);
    cudaGetSymbolAddress((void**)&combWl, g_combWl);
    cudaGetSymbolAddress((void**)&combWsm, g_combWsm);
    cudaGetSymbolAddress((void**)&bEnc, g_bEnc);
    cudaGetSymbolAddress((void**)&bDec, g_bDec);

    cudaFuncSetAttribute(mma_kernel<1, true, true, true>,
                         cudaFuncAttributeMaxDynamicSharedMemorySize, SMEM_TOTAL);
    cudaFuncSetAttribute(mma_kernel<1, true, false, false>,
                         cudaFuncAttributeMaxDynamicSharedMemorySize, SMEM_TOTAL);
    cudaFuncSetAttribute(mma_kernel<2, false, true, false>,
                         cudaFuncAttributeMaxDynamicSharedMemorySize, SMEM_TOTAL);

    init_kernel<<<(B_ * H_ + 255) / 256, 256>>>(input);
    repack_kernel<<<N4H, 256>>>(enc_W_hh, enc_W_ih, dec_W_ih, dec_W_hh, comb_W,
                                enc_b_ih, enc_b_hh, dec_b_ih, dec_b_hh);

    const dim3 grid_gates(N4H / 64, B_ / 64);   // 32 x 16 = 512 blocks
    const dim3 grid_comb(H_ / 64, B_ / 64);     // 8 x 16 = 128 blocks

    // ---------------- encoder ----------------
    float *h_in = hA, *h_out = hB;
    bf16 *hih = hAh, *hil = hAl, *hoh = hBh, *hol = hBl;
    for (int t = 0; t < L_; t++) {
        mma_kernel<1, true, true, true><<<grid_gates, 256, SMEM_TOTAL>>>(
            hih, hil, WencHHh, WencHHl,
            nullptr, nullptr, nullptr, nullptr,
            input + t * D_, L_ * D_, WencIH,
            bEnc, c, c, h_out, hoh, hol, enc + t * H_);
        { float* tp = h_in; h_in = h_out; h_out = tp; }
        { bf16* tp = hih; hih = hoh; hoh = tp; tp = hil; hil = hol; hol = tp; }
    }

    // ---------------- decoder ----------------
    float *x_in = xA, *x_out = xB;
    for (int t = 0; t < T_; t++) {
        attn_kernel<<<B_, 256>>>(x_in, h_in, attn_W, attn_b, enc, attnH, attnL);
        mma_kernel<1, true, false, false><<<grid_comb, 256, SMEM_TOTAL>>>(
            attnH, attnL, combWh, combWl,
            nullptr, nullptr, nullptr, nullptr,
            x_in, D_, combWsm,
            comb_b, nullptr, nullptr, nullptr, combH, combL, nullptr);
        mma_kernel<2, false, true, false><<<grid_gates, 256, SMEM_TOTAL>>>(
            combH, combL, WdecIHh, WdecIHl,
            hih, hil, WdecHHh, WdecHHl,
            nullptr, 0, nullptr,
            bDec, c, c, h_out, hoh, hol, nullptr);
        pred_kernel<<<B_, 128>>>(h_out, out_W, out_b, outp, t, x_out);
        { float* tp = h_in; h_in = h_out; h_out = tp; }
        { bf16* tp = hih; hih = hoh; hoh = tp; tp = hil; hil = hol; hol = tp; }
        { float* tp = x_in; x_in = x_out; x_out = tp; }
    }
}

// round 15
// speedup vs baseline: 1.0333x; 1.0017x over previous
#include <cuda_runtime.h>
#include <cuda_bf16.h>
#include <math.h>
#include <stdint.h>

#define B_  1024
#define L_  50
#define D_  4
#define H_  512
#define T_  30
#define N4H 2048
#define CW  516

typedef __nv_bfloat16 bf16;

// ===================== base-ISA PTX helpers (sm_80+ features only) =====================
__device__ __forceinline__ uint32_t smem_u32(const void* p) {
    uint32_t a;
    asm("{ .reg .u64 t; cvta.to.shared.u64 t, %1; cvt.u32.u64 %0, t; }" : "=r"(a) : "l"(p));
    return a;
}
__device__ __forceinline__ void mma16816(float* d, const uint32_t* a, const uint32_t* b) {
    asm volatile(
        "mma.sync.aligned.m16n8k16.row.col.f32.bf16.bf16.f32 "
        "{%0,%1,%2,%3}, {%4,%5,%6,%7}, {%8,%9}, {%0,%1,%2,%3};"
        : "+f"(d[0]), "+f"(d[1]), "+f"(d[2]), "+f"(d[3])
        : "r"(a[0]), "r"(a[1]), "r"(a[2]), "r"(a[3]), "r"(b[0]), "r"(b[1]));
}
__device__ __forceinline__ void ldsm4(uint32_t* r, uint32_t addr) {
    asm volatile("ldmatrix.sync.aligned.m8n8.x4.shared.b16 {%0,%1,%2,%3}, [%4];"
        : "=r"(r[0]), "=r"(r[1]), "=r"(r[2]), "=r"(r[3]) : "r"(addr));
}
#define CP_ASYNC16(sa, gp) \
    asm volatile("cp.async.ca.shared.global [%0], [%1], 16;" :: "r"(sa), "l"(gp) : "memory")
#define CP_COMMIT() asm volatile("cp.async.commit_group;" ::: "memory")

__device__ __forceinline__ float sigf(float x) { return 1.f / (1.f + __expf(-x)); }
__device__ __forceinline__ void bsplit(float v, bf16& hi, bf16& lo) {
    hi = __float2bfloat16(v);
    lo = __float2bfloat16(v - __bfloat162float(hi));
}

// ============================ persistent device state ============================
__device__ __align__(16) float g_hA[B_ * H_];
__device__ __align__(16) float g_hB[B_ * H_];
__device__ __align__(16) bf16  g_hAh[B_ * H_];
__device__ __align__(16) bf16  g_hAl[B_ * H_];
__device__ __align__(16) bf16  g_hBh[B_ * H_];
__device__ __align__(16) bf16  g_hBl[B_ * H_];
__device__ __align__(16) float g_c[B_ * H_];
__device__ __align__(16) float g_enc[B_ * L_ * H_];
__device__ __align__(16) bf16  g_attnH[B_ * H_];
__device__ __align__(16) bf16  g_attnL[B_ * H_];
__device__ __align__(16) bf16  g_combH[B_ * H_];
__device__ __align__(16) bf16  g_combL[B_ * H_];
__device__ __align__(16) float g_xA[B_ * D_];
__device__ __align__(16) float g_xB[B_ * D_];
// gate-permuted weights for fused LSTM epilogue:
// new col n: chunk=n>>4, w=n&15, gate=((w>>3)<<1)|(w&1), unit=chunk*4+((w>>1)&3)
__device__ __align__(16) bf16  g_WencHHh[N4H * H_];
__device__ __align__(16) bf16  g_WencHHl[N4H * H_];
__device__ __align__(16) bf16  g_WdecIHh[N4H * H_];
__device__ __align__(16) bf16  g_WdecIHl[N4H * H_];
__device__ __align__(16) bf16  g_WdecHHh[N4H * H_];
__device__ __align__(16) bf16  g_WdecHHl[N4H * H_];
__device__ __align__(16) float g_WencIH[N4H * D_];
__device__ __align__(16) bf16  g_combWh[H_ * H_];
__device__ __align__(16) bf16  g_combWl[H_ * H_];
__device__ __align__(16) float g_combWsm[H_ * D_];
__device__ float g_bEnc[N4H];
__device__ float g_bDec[N4H];

// ============================ init / repack ============================
__global__ void init_kernel(const float* __restrict__ input) {
    int idx = blockIdx.x * blockDim.x + threadIdx.x;
    if (idx < B_ * H_) {
        g_hA[idx] = 0.f; g_c[idx] = 0.f;
        g_hAh[idx] = __float2bfloat16(0.f); g_hAl[idx] = __float2bfloat16(0.f);
    }
    if (idx < B_ * D_) {
        int b = idx >> 2, d = idx & 3;
        g_xA[idx] = input[b * (L_ * D_) + (L_ - 1) * D_ + d];
    }
}

__global__ void repack_kernel(const float* __restrict__ encHH, const float* __restrict__ encIH,
                              const float* __restrict__ decIH, const float* __restrict__ decHH,
                              const float* __restrict__ combW,
                              const float* __restrict__ eb1, const float* __restrict__ eb2,
                              const float* __restrict__ db1, const float* __restrict__ db2)
{
    int n = blockIdx.x;                          // new row index 0..2047
    int w = n & 15, chunk = n >> 4;
    int gate = ((w >> 3) << 1) | (w & 1);
    int u = chunk * 4 + ((w >> 1) & 3);
    int src = gate * H_ + u;
    for (int k = threadIdx.x; k < H_; k += blockDim.x) {
        bf16 hi, lo;
        bsplit(encHH[src * H_ + k], hi, lo);
        g_WencHHh[n * H_ + k] = hi; g_WencHHl[n * H_ + k] = lo;
        bsplit(decIH[src * H_ + k], hi, lo);
        g_WdecIHh[n * H_ + k] = hi; g_WdecIHl[n * H_ + k] = lo;
        bsplit(decHH[src * H_ + k], hi, lo);
        g_WdecHHh[n * H_ + k] = hi; g_WdecHHl[n * H_ + k] = lo;
        if (n < H_) {
            bsplit(combW[n * CW + D_ + k], hi, lo);      // natural order for comb
            g_combWh[n * H_ + k] = hi; g_combWl[n * H_ + k] = lo;
        }
    }
    if (threadIdx.x < D_) {
        g_WencIH[n * D_ + threadIdx.x] = encIH[src * D_ + threadIdx.x];
        if (n < H_) g_combWsm[n * D_ + threadIdx.x] = combW[n * CW + threadIdx.x];
    }
    if (threadIdx.x == 0) {
        g_bEnc[n] = eb1[src] + eb2[src];
        g_bDec[n] = db1[src] + db2[src];
    }
}

// ============================ HMMA GEMM (+fused epilogue) ============================
// C[64x64] = A(hi/lo bf16, 64xK) @ W(hi/lo bf16, 64xK)^T via 3x mma.sync.m16n8k16
// per k16 (hi*hi + hi*lo + lo*hi), fp32 accum. 4 warps (128 thr), warp tile 32m x 32n
// (ldsm/mma ratio 0.33). BK=32, cp.async 3-stage ring, SINGLE sync per stage,
// 80B-padded rows. 3 blocks/SM by smem -> 12 warps/SM; 512-block grid.

#define ROW_B   80
#define A_OFF   0                         // Ah rows 0..63
#define AL_OFF  (64 * ROW_B)              // Al rows 64..127
#define BH_OFF  (128 * ROW_B)             // Bh rows 128..191
#define BL_OFF  (192 * ROW_B)             // Bl rows 192..255
#define STAGE_B (256 * ROW_B)             // 20480 bytes per stage
#define SM_BIAS (3 * STAGE_B)             // 61440: 64 floats
#define SM_XS   (SM_BIAS + 256)           // 64 x 4 floats
#define SM_WS   (SM_XS + 1024)            // 64 x 4 floats
#define SMEM_TOTAL (SM_WS + 1024)         // 63744 bytes

template<int NPASS, bool HAS_SMALL, bool LSTM_EPI, bool WRITE_ENC>
__global__ void __launch_bounds__(128, 3)
mma_kernel(const bf16* __restrict__ A0h, const bf16* __restrict__ A0l,
           const bf16* __restrict__ B0h, const bf16* __restrict__ B0l,
           const bf16* __restrict__ A1h, const bf16* __restrict__ A1l,
           const bf16* __restrict__ B1h, const bf16* __restrict__ B1l,
           const float* __restrict__ Asm, int ldasm, const float* __restrict__ Wsm,
           const float* __restrict__ bias,
           const float* __restrict__ c_in, float* __restrict__ c_out,
           float* __restrict__ h_out, bf16* __restrict__ hh_out, bf16* __restrict__ hl_out,
           float* __restrict__ enc_slot)
{
    extern __shared__ char smem[];
    const uint32_t sb = smem_u32(smem);
    const int tid = threadIdx.x;
    const int wid = tid >> 5, lane = tid & 31;
    const int warp_m = wid & 1, warp_n = wid >> 1;    // 2 x 2 warp grid, 32m x 32n each
    const int lane8 = lane & 7, sel = lane >> 3;
    const int gID = lane >> 2, tig = lane & 3;
    const int bn = blockIdx.x * 64;
    const int bm = blockIdx.y * 64;

    float* sbias = (float*)(smem + SM_BIAS);
    float* xs    = (float*)(smem + SM_XS);
    float* ws    = (float*)(smem + SM_WS);

    if (tid < 64) {
        sbias[tid] = bias[bn + tid];
        if (HAS_SMALL) {
            float4 v = *reinterpret_cast<const float4*>(&Wsm[(bn + tid) * 4]);
            ws[tid * 4 + 0] = v.x; ws[tid * 4 + 1] = v.y;
            ws[tid * 4 + 2] = v.z; ws[tid * 4 + 3] = v.w;
        }
    } else if (HAS_SMALL) {
        int r = tid - 64;
        const float* xr = Asm + (size_t)(bm + r) * ldasm;
        xs[r * 4 + 0] = xr[0]; xs[r * 4 + 1] = xr[1];
        xs[r * 4 + 2] = xr[2]; xs[r * 4 + 3] = xr[3];
    }

    float acc[2][4][4];
    #pragma unroll
    for (int mt = 0; mt < 2; mt++)
        #pragma unroll
        for (int nt = 0; nt < 4; nt++)
            #pragma unroll
            for (int c = 0; c < 4; c++) acc[mt][nt][c] = 0.f;

    const int NS = NPASS * 16;

    auto load_stage = [&](int buf, int s) {
        const bool p1 = (NPASS == 2) && (s >= 16);
        const bf16* Ah = p1 ? A1h : A0h;
        const bf16* Al = p1 ? A1l : A0l;
        const bf16* Bh = p1 ? B1h : B0h;
        const bf16* Bl = p1 ? B1l : B0l;
        const int k0 = (s & 15) * 32;
        const uint32_t tb = sb + buf * STAGE_B;
        #pragma unroll
        for (int j = 0; j < 8; j++) {
            const int sIdx = j * 128 + tid;
            const int row = sIdx >> 2, seg = sIdx & 3;      // 32-row uniform range per j
            const bf16* g; int grow;
            if (row < 64)       { g = Ah; grow = bm + row; }
            else if (row < 128) { g = Al; grow = bm + row - 64; }
            else if (row < 192) { g = Bh; grow = bn + row - 128; }
            else                { g = Bl; grow = bn + row - 192; }
            const bf16* gp = g + (size_t)grow * H_ + k0 + seg * 8;
            CP_ASYNC16(tb + row * ROW_B + seg * 16, gp);
        }
        CP_COMMIT();
    };

    auto compute = [&](int buf) {
        const uint32_t tb = sb + buf * STAGE_B;
        #pragma unroll
        for (int kq = 0; kq < 2; kq++) {
            const int kk = kq * 16;
            const int kcol = (kk + ((sel >> 1) << 3)) * 2;
            uint32_t ah[2][4], al[2][4];
            #pragma unroll
            for (int mt = 0; mt < 2; mt++) {
                const int ar = warp_m * 32 + mt * 16 + ((sel & 1) << 3) + lane8;
                uint32_t ra = tb + (uint32_t)(ar * ROW_B) + kcol;
                ldsm4(ah[mt], ra + A_OFF);
                ldsm4(al[mt], ra + AL_OFF);
            }
            const int kcolb = (kk + ((sel & 1) << 3)) * 2;
            uint32_t bh[2][4], bl[2][4];
            #pragma unroll
            for (int p = 0; p < 2; p++) {
                const int br = warp_n * 32 + (2 * p + (sel >> 1)) * 8 + lane8;
                uint32_t rb = tb + (uint32_t)(br * ROW_B) + kcolb;
                ldsm4(bh[p], rb + BH_OFF);
                ldsm4(bl[p], rb + BL_OFF);
            }
            #pragma unroll
            for (int mt = 0; mt < 2; mt++)
                #pragma unroll
                for (int p = 0; p < 2; p++) {
                    mma16816(acc[mt][2 * p],     ah[mt], bh[p]);
                    mma16816(acc[mt][2 * p + 1], ah[mt], bh[p] + 2);
                    mma16816(acc[mt][2 * p],     ah[mt], bl[p]);
                    mma16816(acc[mt][2 * p + 1], ah[mt], bl[p] + 2);
                    mma16816(acc[mt][2 * p],     al[mt], bh[p]);
                    mma16816(acc[mt][2 * p + 1], al[mt], bh[p] + 2);
                }
        }
    };

    load_stage(0, 0);
    if (NS > 1) load_stage(1, 1);
    #pragma unroll 1
    for (int s = 0; s < NS; s++) {
        if (s + 1 < NS) {
            asm volatile("cp.async.wait_group 1;" ::: "memory");   // stage s data arrived
        } else {
            asm volatile("cp.async.wait_group 0;" ::: "memory");
        }
        __syncthreads();            // all data visible; all warps done reading buf (s+2)%3
        if (s + 2 < NS) load_stage((s + 2) % 3, s + 2);
        compute(s % 3);
    }

    // -------------------- epilogue --------------------
    if (LSTM_EPI) {
        #pragma unroll
        for (int mt = 0; mt < 2; mt++) {
            #pragma unroll
            for (int rh = 0; rh < 2; rh++) {           // C-fragment row half (+0 / +8)
                const int rl = warp_m * 32 + mt * 16 + gID + rh * 8;
                const int grow = bm + rl;
                const int ci = rh * 2;
                float x0 = 0.f, x1 = 0.f, x2 = 0.f, x3 = 0.f;
                if (HAS_SMALL) {
                    const float* xr = xs + rl * 4;
                    x0 = xr[0]; x1 = xr[1]; x2 = xr[2]; x3 = xr[3];
                }
                #pragma unroll
                for (int k = 0; k < 2; k++) {
                    const int ni = warp_n * 32 + k * 16 + 2 * tig;   // local col of gate i
                    float pi = acc[mt][2 * k][ci]     + sbias[ni];
                    float pf = acc[mt][2 * k][ci + 1] + sbias[ni + 1];
                    float pg = acc[mt][2 * k + 1][ci]     + sbias[ni + 8];
                    float po = acc[mt][2 * k + 1][ci + 1] + sbias[ni + 9];
                    if (HAS_SMALL) {
                        const float* wi = ws + ni * 4;
                        const float* wf = ws + (ni + 1) * 4;
                        const float* wg = ws + (ni + 8) * 4;
                        const float* wo = ws + (ni + 9) * 4;
                        pi += x0 * wi[0] + x1 * wi[1] + x2 * wi[2] + x3 * wi[3];
                        pf += x0 * wf[0] + x1 * wf[1] + x2 * wf[2] + x3 * wf[3];
                        pg += x0 * wg[0] + x1 * wg[1] + x2 * wg[2] + x3 * wg[3];
                        po += x0 * wo[0] + x1 * wo[1] + x2 * wo[2] + x3 * wo[3];
                    }
                    const int u = (bn >> 2) + warp_n * 8 + k * 4 + tig;
                    const int idx = grow * H_ + u;
                    float cold = c_in[idx];
                    float cn = sigf(pf) * cold + sigf(pi) * tanhf(pg);
                    float hn = sigf(po) * tanhf(cn);
                    c_out[idx] = cn;
                    h_out[idx] = hn;
                    bf16 hh, hl; bsplit(hn, hh, hl);
                    hh_out[idx] = hh; hl_out[idx] = hl;
                    if (WRITE_ENC) enc_slot[grow * (L_ * H_) + u] = hn;
                }
            }
        }
    } else {
        #pragma unroll
        for (int mt = 0; mt < 2; mt++) {
            #pragma unroll
            for (int c = 0; c < 4; c++) {
                const int rl = warp_m * 32 + mt * 16 + gID + (c >> 1) * 8;
                const int grow = bm + rl;
                float x0 = 0.f, x1 = 0.f, x2 = 0.f, x3 = 0.f;
                if (HAS_SMALL) {
                    const float* xr = xs + rl * 4;
                    x0 = xr[0]; x1 = xr[1]; x2 = xr[2]; x3 = xr[3];
                }
                #pragma unroll
                for (int nt = 0; nt < 4; nt++) {
                    const int nl = warp_n * 32 + nt * 8 + 2 * tig + (c & 1);
                    float v = acc[mt][nt][c] + sbias[nl];
                    if (HAS_SMALL) {
                        const float* w = ws + nl * 4;
                        v += x0 * w[0] + x1 * w[1] + x2 * w[2] + x3 * w[3];
                    }
                    v = fmaxf(v, 0.f);
                    const int idx = grow * H_ + bn + nl;
                    bf16 hh, hl; bsplit(v, hh, hl);
                    hh_out[idx] = hh; hl_out[idx] = hl;
                }
            }
        }
    }
}

// ============================ attention (fp32) ============================
// h_r[b,k] = h[2k + (b>=512), b & 511]  (reference's reshape/transpose quirk)
__global__ void __launch_bounds__(256)
attn_kernel(const float* __restrict__ x, const float* __restrict__ h,
            const float* __restrict__ attn_W, const float* __restrict__ attn_b,
            const float* __restrict__ enc, bf16* __restrict__ outH, bf16* __restrict__ outL)
{
    __shared__ float v[H_ + D_];
    __shared__ float wts[64];
    const int b = blockIdx.x;
    const int tid = threadIdx.x;

    if (tid < D_) v[tid] = x[b * D_ + tid];
    {
        int brow = b >> 9, bcol = b & 511;
        for (int k = tid; k < H_; k += 256)
            v[D_ + k] = h[(2 * k + brow) * H_ + bcol];
    }
    __syncthreads();

    const int warp = tid >> 5, lane = tid & 31;
    for (int l = warp; l < L_; l += 8) {
        const float* wrow = attn_W + l * (H_ + D_);
        float s = 0.f;
        for (int k = lane; k < H_ + D_; k += 32) s += v[k] * wrow[k];
        #pragma unroll
        for (int off = 16; off; off >>= 1) s += __shfl_xor_sync(0xffffffffu, s, off);
        if (lane == 0) wts[l] = s + attn_b[l];
    }
    __syncthreads();

    if (tid < 32) {
        float v1 = (tid < L_) ? wts[tid] : -1e30f;
        float v2 = (tid + 32 < L_) ? wts[tid + 32] : -1e30f;
        float m = fmaxf(v1, v2);
        #pragma unroll
        for (int off = 16; off; off >>= 1) m = fmaxf(m, __shfl_xor_sync(0xffffffffu, m, off));
        float e1 = (tid < L_) ? __expf(v1 - m) : 0.f;
        float e2 = (tid + 32 < L_) ? __expf(v2 - m) : 0.f;
        float s = e1 + e2;
        #pragma unroll
        for (int off = 16; off; off >>= 1) s += __shfl_xor_sync(0xffffffffu, s, off);
        float inv = 1.f / s;
        if (tid < L_) wts[tid] = e1 * inv;
        if (tid + 32 < L_) wts[tid + 32] = e2 * inv;
    }
    __syncthreads();

    const float* e = enc + (size_t)b * (L_ * H_);
    for (int j = tid; j < H_; j += 256) {
        float s = 0.f;
        #pragma unroll
        for (int l = 0; l < L_; l++) s += wts[l] * e[l * H_ + j];
        bf16 hi, lo; bsplit(s, hi, lo);
        outH[b * H_ + j] = hi; outL[b * H_ + j] = lo;
    }
}

// ============================ pred ============================
__global__ void pred_kernel(const float* __restrict__ h, const float* __restrict__ out_W,
                            const float* __restrict__ out_b, float* __restrict__ out,
                            int t, float* __restrict__ x_next)
{
    const int b = blockIdx.x;
    const int warp = threadIdx.x >> 5, lane = threadIdx.x & 31;
    const float* hr = h + b * H_;
    const float* w = out_W + warp * H_;
    float s = 0.f;
    #pragma unroll
    for (int k = lane; k < H_; k += 32) s += hr[k] * w[k];
    #pragma unroll
    for (int off = 16; off; off >>= 1) s += __shfl_xor_sync(0xffffffffu, s, off);
    if (lane == 0) {
        float p = s + out_b[warp];
        out[(b * T_ + t) * D_ + warp] = p;
        x_next[b * D_ + warp] = p;
    }
}

// ============================ launch ============================
extern "C" void kernel_launch(void* const* d_in, const int* in_sizes, int n_in,
                              void* d_out, int out_size)
{
    int base = (n_in >= 16 && in_sizes[1] == 1) ? 2 : 1;

    const float* input    = (const float*)d_in[0];
    const float* enc_W_ih = (const float*)d_in[base + 0];
    const float* enc_W_hh = (const float*)d_in[base + 1];
    const float* enc_b_ih = (const float*)d_in[base + 2];
    const float* enc_b_hh = (const float*)d_in[base + 3];
    const float* attn_W   = (const float*)d_in[base + 4];
    const float* attn_b   = (const float*)d_in[base + 5];
    const float* comb_W   = (const float*)d_in[base + 6];
    const float* comb_b   = (const float*)d_in[base + 7];
    const float* dec_W_ih = (const float*)d_in[base + 8];
    const float* dec_W_hh = (const float*)d_in[base + 9];
    const float* dec_b_ih = (const float*)d_in[base + 10];
    const float* dec_b_hh = (const float*)d_in[base + 11];
    const float* out_W    = (const float*)d_in[base + 12];
    const float* out_b    = (const float*)d_in[base + 13];
    float* outp = (float*)d_out;

    float *hA, *hB, *c, *enc, *xA, *xB, *WencIH, *combWsm, *bEnc, *bDec;
    bf16 *hAh, *hAl, *hBh, *hBl, *attnH, *attnL, *combH, *combL;
    bf16 *WencHHh, *WencHHl, *WdecIHh, *WdecIHl, *WdecHHh, *WdecHHl, *combWh, *combWl;
    cudaGetSymbolAddress((void**)&hA, g_hA);
    cudaGetSymbolAddress((void**)&hB, g_hB);
    cudaGetSymbolAddress((void**)&hAh, g_hAh);
    cudaGetSymbolAddress((void**)&hAl, g_hAl);
    cudaGetSymbolAddress((void**)&hBh, g_hBh);
    cudaGetSymbolAddress((void**)&hBl, g_hBl);
    cudaGetSymbolAddress((void**)&c, g_c);
    cudaGetSymbolAddress((void**)&enc, g_enc);
    cudaGetSymbolAddress((void**)&attnH, g_attnH);
    cudaGetSymbolAddress((void**)&attnL, g_attnL);
    cudaGetSymbolAddress((void**)&combH, g_combH);
    cudaGetSymbolAddress((void**)&combL, g_combL);
    cudaGetSymbolAddress((void**)&xA, g_xA);
    cudaGetSymbolAddress((void**)&xB, g_xB);
    cudaGetSymbolAddress((void**)&WencHHh, g_WencHHh);
    cudaGetSymbolAddress((void**)&WencHHl, g_WencHHl);
    cudaGetSymbolAddress((void**)&WdecIHh, g_WdecIHh);
    cudaGetSymbolAddress((void**)&WdecIHl, g_WdecIHl);
    cudaGetSymbolAddress((void**)&WdecHHh, g_WdecHHh);
    cudaGetSymbolAddress((void**)&WdecHHl, g_WdecHHl);
    cudaGetSymbolAddress((void**)&WencIH, g_WencIH);
    cudaGetSymbolAddress((void**)&combWh, g_combWh);
    cudaGetSymbolAddress((void**)&combWl, g_combWl);
    cudaGetSymbolAddress((void**)&combWsm, g_combWsm);
    cudaGetSymbolAddress((void**)&bEnc, g_bEnc);
    cudaGetSymbolAddress((void**)&bDec, g_bDec);

    cudaFuncSetAttribute(mma_kernel<1, true, true, true>,
                         cudaFuncAttributeMaxDynamicSharedMemorySize, SMEM_TOTAL);
    cudaFuncSetAttribute(mma_kernel<1, true, false, false>,
                         cudaFuncAttributeMaxDynamicSharedMemorySize, SMEM_TOTAL);
    cudaFuncSetAttribute(mma_kernel<2, false, true, false>,
                         cudaFuncAttributeMaxDynamicSharedMemorySize, SMEM_TOTAL);

    init_kernel<<<(B_ * H_ + 255) / 256, 256>>>(input);
    repack_kernel<<<N4H, 256>>>(enc_W_hh, enc_W_ih, dec_W_ih, dec_W_hh, comb_W,
                                enc_b_ih, enc_b_hh, dec_b_ih, dec_b_hh);

    const dim3 grid_gates(N4H / 64, B_ / 64);   // 32 x 16 = 512 blocks
    const dim3 grid_comb(H_ / 64, B_ / 64);     // 8 x 16 = 128 blocks

    // ---------------- encoder ----------------
    float *h_in = hA, *h_out = hB;
    bf16 *hih = hAh, *hil = hAl, *hoh = hBh, *hol = hBl;
    for (int t = 0; t < L_; t++) {
        mma_kernel<1, true, true, true><<<grid_gates, 128, SMEM_TOTAL>>>(
            hih, hil, WencHHh, WencHHl,
            nullptr, nullptr, nullptr, nullptr,
            input + t * D_, L_ * D_, WencIH,
            bEnc, c, c, h_out, hoh, hol, enc + t * H_);
        { float* tp = h_in; h_in = h_out; h_out = tp; }
        { bf16* tp = hih; hih = hoh; hoh = tp; tp = hil; hil = hol; hol = tp; }
    }

    // ---------------- decoder ----------------
    float *x_in = xA, *x_out = xB;
    for (int t = 0; t < T_; t++) {
        attn_kernel<<<B_, 256>>>(x_in, h_in, attn_W, attn_b, enc, attnH, attnL);
        mma_kernel<1, true, false, false><<<grid_comb, 128, SMEM_TOTAL>>>(
            attnH, attnL, combWh, combWl,
            nullptr, nullptr, nullptr, nullptr,
            x_in, D_, combWsm,
            comb_b, nullptr, nullptr, nullptr, combH, combL, nullptr);
        mma_kernel<2, false, true, false><<<grid_gates, 128, SMEM_TOTAL>>>(
            combH, combL, WdecIHh, WdecIHl,
            hih, hil, WdecHHh, WdecHHl,
            nullptr, 0, nullptr,
            bDec, c, c, h_out, hoh, hol, nullptr);
        pred_kernel<<<B_, 128>>>(h_out, out_W, out_b, outp, t, x_out);
        { float* tp = h_in; h_in = h_out; h_out = tp; }
        { bf16* tp = hih; hih = hoh; hoh = tp; tp = hil; hil = hol; hol = tp; }
        { float* tp = x_in; x_in = x_out; x_out = tp; }
    }
}